// round 11
// baseline (speedup 1.0000x reference)
#include <cuda_runtime.h>
#include <cuda_bf16.h>

// Batched LSAP -> mean of matched original entries, one warp per matrix.
// Normalization skipped (monotone affine => same optimal assignment).
//
// Phase A: column reduction (v[j]=min_i C[i,j], argmin rows claimed).
// Phase B: 2x augmenting row reduction sweeps (JV init).
// Phase C: shortest augmenting path for remaining rows, barrier-free:
//   - single __reduce_min_sync on (truncated value | column) packed key
//   - exact minVal via one shfl from the winner lane
//   - per-column working duals / frozen values / row4col / du in SHARED,
//     updated by single predicated STS (no register-array SET4 trees)
//   - frozen columns self-exclude: sp<-1e20 and vw<- -1e25 makes future
//     reduced costs ~+1e25, so value+path updates need no masks.
// Finish folded in: atomic completion counter, last CTA reduces g_partial
// in fixed index order (deterministic), resets counter for graph replay.

#define NN 128
#define BATCH 128
#define INF_F    1e30f
#define SPFROZEN 1e20f
#define VPOISON  -1e25f
#define DU_SENT  -1e30f
#define FULL 0xffffffffu

__device__ float g_partial[BATCH];
__device__ unsigned g_count = 0;

// order-preserving float <-> uint bijection
__device__ __forceinline__ unsigned fford(float f) {
    unsigned b = __float_as_uint(f);
    return b ^ (unsigned)(((int)b >> 31) | 0x80000000);
}
__device__ __forceinline__ float ffunord(unsigned u) {
    unsigned b = u ^ (unsigned)(((int)(~u) >> 31) | 0x80000000);
    return __uint_as_float(b);
}

#define SEL4(s, a0, a1, a2, a3) ((s) < 2 ? ((s) == 0 ? (a0) : (a1)) \
                                         : ((s) == 2 ? (a2) : (a3)))
#define SET4(s, a0, a1, a2, a3, val) do {            \
    if      ((s) == 0) a0 = (val);                   \
    else if ((s) == 1) a1 = (val);                   \
    else if ((s) == 2) a2 = (val);                   \
    else               a3 = (val); } while (0)

__global__ __launch_bounds__(32, 1)
void lsap_warp_kernel(const float* __restrict__ D, float* __restrict__ out) {
    extern __shared__ float Cs[];              // NN*NN floats (64KB)
    __shared__ float u_s[NN], vw_s[NN], du_s[NN], fz_s[NN];
    __shared__ int   r4c_s[NN], c4r_s[NN], claim_s[NN];

    const int lane = threadIdx.x;
    const int b    = blockIdx.x;

    // ---- load cost matrix (coalesced float4) ----
    {
        const float4* src = reinterpret_cast<const float4*>(D + (size_t)b * NN * NN);
        float4* dst = reinterpret_cast<float4*>(Cs);
        #pragma unroll 8
        for (int k = lane; k < NN * NN / 4; k += 32) dst[k] = src[k];
    }
    #pragma unroll
    for (int k = 0; k < 4; ++k) {
        u_s[lane + 32 * k]     = 0.0f;
        claim_s[lane + 32 * k] = 0x7FFFFFFF;
        r4c_s[lane + 32 * k]   = -1;
        c4r_s[lane + 32 * k]   = -1;
    }
    __syncwarp();

    // ================= Phase A: column reduction =================
    float cm0 = INF_F, cm1 = INF_F, cm2 = INF_F, cm3 = INF_F;
    int   am0 = 0, am1 = 0, am2 = 0, am3 = 0;
    #pragma unroll 4
    for (int i = 0; i < NN; ++i) {
        const float* row = Cs + i * NN;
        float a0 = row[lane], a1 = row[lane + 32], a2 = row[lane + 64], a3 = row[lane + 96];
        if (a0 < cm0) { cm0 = a0; am0 = i; }
        if (a1 < cm1) { cm1 = a1; am1 = i; }
        if (a2 < cm2) { cm2 = a2; am2 = i; }
        if (a3 < cm3) { cm3 = a3; am3 = i; }
    }
    float v0 = cm0, v1 = cm1, v2 = cm2, v3 = cm3;   // column duals (registers)

    atomicMin(&claim_s[am0], lane);
    atomicMin(&claim_s[am1], lane + 32);
    atomicMin(&claim_s[am2], lane + 64);
    atomicMin(&claim_s[am3], lane + 96);
    __syncwarp();
    if (claim_s[am0] == lane)      { r4c_s[lane]      = am0; c4r_s[am0] = lane; }
    if (claim_s[am1] == lane + 32) { r4c_s[lane + 32] = am1; c4r_s[am1] = lane + 32; }
    if (claim_s[am2] == lane + 64) { r4c_s[lane + 64] = am2; c4r_s[am2] = lane + 64; }
    if (claim_s[am3] == lane + 96) { r4c_s[lane + 96] = am3; c4r_s[am3] = lane + 96; }
    __syncwarp();
    int c4r0 = c4r_s[lane],      c4r1 = c4r_s[lane + 32],
        c4r2 = c4r_s[lane + 64], c4r3 = c4r_s[lane + 96];
    __syncwarp();

    // ================= Phase B: augmenting row reduction (2 sweeps) =========
    for (int pass = 0; pass < 2; ++pass) {
        for (int i = 0; i < NN; ++i) {
            const int mycI = SEL4(i >> 5, c4r0, c4r1, c4r2, c4r3);
            const int ci   = __shfl_sync(FULL, mycI, i & 31);
            if (ci >= 0) continue;                        // row assigned

            const float* row = Cs + i * NN;
            const float t0 = row[lane]      - v0;
            const float t1 = row[lane + 32] - v1;
            const float t2 = row[lane + 64] - v2;
            const float t3 = row[lane + 96] - v3;
            const float bv = fminf(fminf(t0, t1), fminf(t2, t3));
            const int   bk = (t0 == bv) ? 0 : ((t1 == bv) ? 1 : ((t2 == bv) ? 2 : 3));
            unsigned key = (fford(bv) & 0xFFFFFF80u) | (unsigned)((bk << 5) | lane);
            key = __reduce_min_sync(FULL, key);
            const int j1 = (int)(key & 127u);
            const float cand = SEL4(j1 >> 5, t0, t1, t2, t3);
            const float min1 = __shfl_sync(FULL, cand, j1 & 31);   // exact

            float e0 = t0, e1 = t1, e2 = t2, e3 = t3;
            if (lane == (j1 & 31)) SET4(j1 >> 5, e0, e1, e2, e3, INF_F);
            const float bv2  = fminf(fminf(e0, e1), fminf(e2, e3));
            const float min2 = ffunord(__reduce_min_sync(FULL, fford(bv2)));  // exact

            const int kprev = r4c_s[j1];
            if (lane == 0) { u_s[i] = min2; r4c_s[j1] = i; }
            if (lane == (j1 & 31) && min1 < min2) {
                const float nv = SEL4(j1 >> 5, v0, v1, v2, v3) - (min2 - min1);
                SET4(j1 >> 5, v0, v1, v2, v3, nv);
            }
            if (lane == (i & 31)) SET4(i >> 5, c4r0, c4r1, c4r2, c4r3, j1);
            if (kprev >= 0 && lane == (kprev & 31))
                SET4(kprev >> 5, c4r0, c4r1, c4r2, c4r3, -1);
            __syncwarp();
        }
    }
    __syncwarp();

    // ================= Phase C: shortest augmenting path ====================
    for (int cur = 0; cur < NN; ++cur) {
        const int mycC = SEL4(cur >> 5, c4r0, c4r1, c4r2, c4r3);
        if (__shfl_sync(FULL, mycC, cur & 31) >= 0) continue;

        float sp0 = INF_F, sp1 = INF_F, sp2 = INF_F, sp3 = INF_F;
        int   p0 = -1, p1 = -1, p2 = -1, p3 = -1;
        vw_s[lane]      = v0;  vw_s[lane + 32] = v1;
        vw_s[lane + 64] = v2;  vw_s[lane + 96] = v3;
        du_s[lane]      = DU_SENT;  du_s[lane + 32] = DU_SENT;
        du_s[lane + 64] = DU_SENT;  du_s[lane + 96] = DU_SENT;
        __syncwarp();
        if (lane == 0) du_s[cur] = 0.0f;      // u[cur] += mf at phase end

        float mv = 0.0f;
        int   i  = cur;
        int   sink;

        while (true) {
            const float ui = u_s[i];
            const float* Crow = Cs + i * NN;
            const float q0 = Crow[lane]      - vw_s[lane];
            const float q1 = Crow[lane + 32] - vw_s[lane + 32];
            const float q2 = Crow[lane + 64] - vw_s[lane + 64];
            const float q3 = Crow[lane + 96] - vw_s[lane + 96];
            const float c  = mv - ui;
            const float r0 = q0 + c, r1 = q1 + c, r2 = q2 + c, r3 = q3 + c;
            // frozen slots: sp=1e20, r~+1e25 -> never update, never win
            if (r0 < sp0) p0 = i;   sp0 = fminf(sp0, r0);
            if (r1 < sp1) p1 = i;   sp1 = fminf(sp1, r1);
            if (r2 < sp2) p2 = i;   sp2 = fminf(sp2, r2);
            if (r3 < sp3) p3 = i;   sp3 = fminf(sp3, r3);

            const float bv = fminf(fminf(sp0, sp1), fminf(sp2, sp3));
            const int   bk = (sp0 == bv) ? 0 : ((sp1 == bv) ? 1 : ((sp2 == bv) ? 2 : 3));
            unsigned key = (fford(bv) & 0xFFFFFF80u) | (unsigned)((bk << 5) | lane);
            key = __reduce_min_sync(FULL, key);
            const int j  = (int)(key & 127u);
            const int jl = j & 31, js = j >> 5;
            const float cand = SEL4(js, sp0, sp1, sp2, sp3);
            mv = __shfl_sync(FULL, cand, jl);               // exact popped value
            const int r4 = r4c_s[j];
            if (lane == jl) {                               // freeze column j
                vw_s[j] = VPOISON;
                fz_s[j] = mv;
                SET4(js, sp0, sp1, sp2, sp3, SPFROZEN);
            }
            if (r4 < 0) { sink = j; break; }
            if (lane == 0) du_s[r4] = mv;                   // row r4 enters SR
            i = r4;
        }

        __syncwarp();
        // dual updates (scipy _lsap closed form)
        const float mf = mv;
        {
            float d;
            d = du_s[lane];      if (d > -1e29f) u_s[lane]      += mf - d;
            d = du_s[lane + 32]; if (d > -1e29f) u_s[lane + 32] += mf - d;
            d = du_s[lane + 64]; if (d > -1e29f) u_s[lane + 64] += mf - d;
            d = du_s[lane + 96]; if (d > -1e29f) u_s[lane + 96] += mf - d;
        }
        if (vw_s[lane]      == VPOISON) v0 -= mf - fz_s[lane];
        if (vw_s[lane + 32] == VPOISON) v1 -= mf - fz_s[lane + 32];
        if (vw_s[lane + 64] == VPOISON) v2 -= mf - fz_s[lane + 64];
        if (vw_s[lane + 96] == VPOISON) v3 -= mf - fz_s[lane + 96];

        // augment alternating path
        int j = sink;
        while (true) {
            const int sj  = j >> 5;
            const int myp = SEL4(sj, p0, p1, p2, p3);
            const int ii  = __shfl_sync(FULL, myp, j & 31);
            if (lane == 0) r4c_s[j] = ii;
            const int si  = ii >> 5;
            const int myc = SEL4(si, c4r0, c4r1, c4r2, c4r3);
            const int jn  = __shfl_sync(FULL, myc, ii & 31);
            if (lane == (ii & 31)) SET4(si, c4r0, c4r1, c4r2, c4r3, j);
            j = jn;
            if (ii == cur) break;
        }
        __syncwarp();
    }

    // ---- sum matched original entries, then cross-CTA completion ----
    float m = Cs[(lane)      * NN + c4r0]
            + Cs[(lane + 32) * NN + c4r1]
            + Cs[(lane + 64) * NN + c4r2]
            + Cs[(lane + 96) * NN + c4r3];
    #pragma unroll
    for (int off = 16; off > 0; off >>= 1)
        m += __shfl_down_sync(FULL, m, off);

    int last = 0;
    if (lane == 0) {
        g_partial[b] = m;
        __threadfence();
        last = (atomicAdd(&g_count, 1u) == BATCH - 1);
    }
    if (__shfl_sync(FULL, last, 0)) {
        __threadfence();
        volatile float* gp = g_partial;
        float s = gp[lane] + gp[lane + 32] + gp[lane + 64] + gp[lane + 96];
        #pragma unroll
        for (int off = 16; off > 0; off >>= 1)
            s += __shfl_down_sync(FULL, s, off);
        if (lane == 0) {
            out[0] = s * (1.0f / (float)(NN * BATCH));
            g_count = 0;                       // reset for next graph replay
        }
    }
}

extern "C" void kernel_launch(void* const* d_in, const int* in_sizes, int n_in,
                              void* d_out, int out_size) {
    (void)in_sizes; (void)n_in; (void)out_size;
    const float* D = (const float*)d_in[0];
    float* out = (float*)d_out;

    const int smem = NN * NN * (int)sizeof(float);   // 64KB dynamic
    cudaFuncSetAttribute(lsap_warp_kernel,
                         cudaFuncAttributeMaxDynamicSharedMemorySize, smem);

    lsap_warp_kernel<<<BATCH, 32, smem>>>(D, out);
}

// round 12
// speedup vs baseline: 1.0351x; 1.0351x over previous
#include <cuda_runtime.h>
#include <cuda_bf16.h>

// Batched LSAP -> mean of matched original entries, one warp per matrix.
// Normalization skipped (monotone affine => same optimal assignment).
//
// Column/row ownership: lane L owns columns {4L..4L+3} and rows {4L..4L+3}
// (slot = idx&3, owner lane = idx>>2) so row scans are single LDS.128.
// Column duals v live in REGISTERS; the Dijkstra working copy w starts at v
// and freezing column j sets w_slot = -1e30, which makes future reduced costs
// rm = C + (c - w) saturate to exactly +1e30: frozen columns self-exclude
// from fmin, predecessor updates, and the argmin WITHOUT any masking ops.
// Argmin: per-slot packed keys (truncated ordered-float | column) + UMIN tree
// + one __reduce_min_sync; exact popped value mv and row4col[j] (register-
// resident at the owner) return via two overlapped SHFLs.

#define NN 128
#define BATCH 128
#define INF_F   1e30f
#define NEG_BIG -1e30f
#define DU_SENT -1e30f
#define FULL 0xffffffffu

__device__ float g_partial[BATCH];
__device__ unsigned g_count = 0;

// order-preserving float <-> uint bijection
__device__ __forceinline__ unsigned fford(float f) {
    unsigned b = __float_as_uint(f);
    return b ^ (unsigned)(((int)b >> 31) | 0x80000000);
}
__device__ __forceinline__ float ffunord(unsigned u) {
    unsigned b = u ^ (unsigned)(((int)(~u) >> 31) | 0x80000000);
    return __uint_as_float(b);
}

#define SEL4(s, a0, a1, a2, a3) ((s) < 2 ? ((s) == 0 ? (a0) : (a1)) \
                                         : ((s) == 2 ? (a2) : (a3)))
#define SET4(s, a0, a1, a2, a3, val) do {            \
    if      ((s) == 0) a0 = (val);                   \
    else if ((s) == 1) a1 = (val);                   \
    else if ((s) == 2) a2 = (val);                   \
    else               a3 = (val); } while (0)

__global__ __launch_bounds__(32, 1)
void lsap_warp_kernel(const float* __restrict__ D, float* __restrict__ out) {
    extern __shared__ float Cs[];              // NN*NN floats (64KB)
    __shared__ float u_s[NN], du_s[NN], fz_s[NN];
    __shared__ int   claim_s[NN], c4r_s[NN];

    const int lane = threadIdx.x;
    const int b    = blockIdx.x;
    const int base = lane << 2;                // first owned index
    const unsigned jid0 = base, jid1 = base + 1, jid2 = base + 2, jid3 = base + 3;

    // ---- load cost matrix (coalesced float4) ----
    {
        const float4* src = reinterpret_cast<const float4*>(D + (size_t)b * NN * NN);
        float4* dst = reinterpret_cast<float4*>(Cs);
        #pragma unroll 8
        for (int k = lane; k < NN * NN / 4; k += 32) dst[k] = src[k];
    }
    *reinterpret_cast<float4*>(u_s + base) = make_float4(0.f, 0.f, 0.f, 0.f);
    *reinterpret_cast<int4*>(claim_s + base) =
        make_int4(0x7FFFFFFF, 0x7FFFFFFF, 0x7FFFFFFF, 0x7FFFFFFF);
    *reinterpret_cast<int4*>(c4r_s + base) = make_int4(-1, -1, -1, -1);
    __syncwarp();

    // ================= Phase A: column reduction =================
    float cm0 = INF_F, cm1 = INF_F, cm2 = INF_F, cm3 = INF_F;
    int   am0 = 0, am1 = 0, am2 = 0, am3 = 0;
    #pragma unroll 4
    for (int i = 0; i < NN; ++i) {
        const float4 cr = *reinterpret_cast<const float4*>(Cs + i * NN + base);
        if (cr.x < cm0) { cm0 = cr.x; am0 = i; }
        if (cr.y < cm1) { cm1 = cr.y; am1 = i; }
        if (cr.z < cm2) { cm2 = cr.z; am2 = i; }
        if (cr.w < cm3) { cm3 = cr.w; am3 = i; }
    }
    float v0 = cm0, v1 = cm1, v2 = cm2, v3 = cm3;   // column duals (registers)

    atomicMin(&claim_s[am0], base);
    atomicMin(&claim_s[am1], base + 1);
    atomicMin(&claim_s[am2], base + 2);
    atomicMin(&claim_s[am3], base + 3);
    __syncwarp();
    int r4c0 = -1, r4c1 = -1, r4c2 = -1, r4c3 = -1;   // row4col (by column)
    if (claim_s[am0] == base)     { r4c0 = am0; c4r_s[am0] = base; }
    if (claim_s[am1] == base + 1) { r4c1 = am1; c4r_s[am1] = base + 1; }
    if (claim_s[am2] == base + 2) { r4c2 = am2; c4r_s[am2] = base + 2; }
    if (claim_s[am3] == base + 3) { r4c3 = am3; c4r_s[am3] = base + 3; }
    __syncwarp();
    const int4 ct = *reinterpret_cast<const int4*>(c4r_s + base);
    int c4r0 = ct.x, c4r1 = ct.y, c4r2 = ct.z, c4r3 = ct.w;  // col4row (by row)
    __syncwarp();

    // ================= Phase B: augmenting row reduction (2 sweeps) =========
    for (int pass = 0; pass < 2; ++pass) {
        for (int i = 0; i < NN; ++i) {
            const int mycI = SEL4(i & 3, c4r0, c4r1, c4r2, c4r3);
            if (__shfl_sync(FULL, mycI, i >> 2) >= 0) continue;  // row assigned

            const float4 cr = *reinterpret_cast<const float4*>(Cs + i * NN + base);
            const float t0 = cr.x - v0, t1 = cr.y - v1;
            const float t2 = cr.z - v2, t3 = cr.w - v3;
            unsigned k0 = (fford(t0) & 0xFFFFFF80u) | jid0;
            unsigned k1 = (fford(t1) & 0xFFFFFF80u) | jid1;
            unsigned k2 = (fford(t2) & 0xFFFFFF80u) | jid2;
            unsigned k3 = (fford(t3) & 0xFFFFFF80u) | jid3;
            unsigned key = min(min(k0, k1), min(k2, k3));
            key = __reduce_min_sync(FULL, key);
            const int j1 = (int)(key & 127u), s1 = j1 & 3, l1 = j1 >> 2;
            const float candt = SEL4(s1, t0, t1, t2, t3);
            const float min1  = __shfl_sync(FULL, candt, l1);   // exact

            float e0 = t0, e1 = t1, e2 = t2, e3 = t3;
            if (lane == l1) SET4(s1, e0, e1, e2, e3, INF_F);
            const float bv2  = fminf(fminf(e0, e1), fminf(e2, e3));
            const float min2 = ffunord(__reduce_min_sync(FULL, fford(bv2)));  // exact

            const int candr = SEL4(s1, r4c0, r4c1, r4c2, r4c3);
            const int kprev = __shfl_sync(FULL, candr, l1);
            if (lane == 0) u_s[i] = min2;
            if (lane == l1) {
                SET4(s1, r4c0, r4c1, r4c2, r4c3, i);
                if (min1 < min2) {
                    const float nv = SEL4(s1, v0, v1, v2, v3) - (min2 - min1);
                    SET4(s1, v0, v1, v2, v3, nv);
                }
            }
            if (lane == (i >> 2)) SET4(i & 3, c4r0, c4r1, c4r2, c4r3, j1);
            if (kprev >= 0 && lane == (kprev >> 2))
                SET4(kprev & 3, c4r0, c4r1, c4r2, c4r3, -1);
        }
    }
    __syncwarp();

    // ================= Phase C: shortest augmenting path ====================
    for (int cur = 0; cur < NN; ++cur) {
        const int mycC = SEL4(cur & 3, c4r0, c4r1, c4r2, c4r3);
        if (__shfl_sync(FULL, mycC, cur >> 2) >= 0) continue;

        float sp0 = INF_F, sp1 = INF_F, sp2 = INF_F, sp3 = INF_F;
        int   p0 = 0, p1 = 0, p2 = 0, p3 = 0;        // set before any use
        float w0 = v0, w1 = v1, w2 = v2, w3 = v3;    // working duals (registers)
        *reinterpret_cast<float4*>(du_s + base) =
            make_float4(DU_SENT, DU_SENT, DU_SENT, DU_SENT);
        __syncwarp();
        if (lane == 0) du_s[cur] = 0.0f;             // u[cur] += mf at phase end

        float mv = 0.0f;
        int   i  = cur;
        int   sink;

        while (true) {
            const float c = mv - u_s[i];
            const float4 cr = *reinterpret_cast<const float4*>(Cs + i * NN + base);
            // frozen slots: w=-1e30 -> rm saturates to exactly 1e30 (absorbed)
            const float rm0 = cr.x + (c - w0);
            const float rm1 = cr.y + (c - w1);
            const float rm2 = cr.z + (c - w2);
            const float rm3 = cr.w + (c - w3);
            if (rm0 < sp0) p0 = i;  sp0 = fminf(sp0, rm0);
            if (rm1 < sp1) p1 = i;  sp1 = fminf(sp1, rm1);
            if (rm2 < sp2) p2 = i;  sp2 = fminf(sp2, rm2);
            if (rm3 < sp3) p3 = i;  sp3 = fminf(sp3, rm3);

            unsigned k0 = (fford(sp0) & 0xFFFFFF80u) | jid0;
            unsigned k1 = (fford(sp1) & 0xFFFFFF80u) | jid1;
            unsigned k2 = (fford(sp2) & 0xFFFFFF80u) | jid2;
            unsigned k3 = (fford(sp3) & 0xFFFFFF80u) | jid3;
            unsigned key = min(min(k0, k1), min(k2, k3));
            key = __reduce_min_sync(FULL, key);
            const int j = (int)(key & 127u), js = j & 3, jl = j >> 2;
            const float candf = SEL4(js, sp0, sp1, sp2, sp3);
            const int   candr = SEL4(js, r4c0, r4c1, r4c2, r4c3);
            mv = __shfl_sync(FULL, candf, jl);              // exact popped value
            const int r4 = __shfl_sync(FULL, candr, jl);    // row4col[j]
            if (lane == jl) {                               // freeze column j
                fz_s[j] = candf;                            // exact frozen value
                SET4(js, sp0, sp1, sp2, sp3, INF_F);
                SET4(js, w0, w1, w2, w3, NEG_BIG);
            }
            if (r4 < 0) { sink = j; break; }
            if (lane == 0) du_s[r4] = mv;                   // row r4 enters SR
            i = r4;
        }

        __syncwarp();
        // dual updates (scipy _lsap closed form)
        const float mf = mv;
        {
            const float4 du = *reinterpret_cast<const float4*>(du_s + base);
            float4 uu = *reinterpret_cast<float4*>(u_s + base);
            if (du.x > -1e29f) uu.x += mf - du.x;
            if (du.y > -1e29f) uu.y += mf - du.y;
            if (du.z > -1e29f) uu.z += mf - du.z;
            if (du.w > -1e29f) uu.w += mf - du.w;
            *reinterpret_cast<float4*>(u_s + base) = uu;
        }
        {
            const float4 fz = *reinterpret_cast<const float4*>(fz_s + base);
            if (w0 == NEG_BIG) v0 -= mf - fz.x;
            if (w1 == NEG_BIG) v1 -= mf - fz.y;
            if (w2 == NEG_BIG) v2 -= mf - fz.z;
            if (w3 == NEG_BIG) v3 -= mf - fz.w;
        }

        // augment alternating path (cooperative shfl walk)
        int j = sink;
        while (true) {
            const int sj = j & 3, lj = j >> 2;
            const int myp = SEL4(sj, p0, p1, p2, p3);
            const int ii  = __shfl_sync(FULL, myp, lj);      // i = path[j]
            if (lane == lj) SET4(sj, r4c0, r4c1, r4c2, r4c3, ii);
            const int si = ii & 3, li = ii >> 2;
            const int myc = SEL4(si, c4r0, c4r1, c4r2, c4r3);
            const int jn  = __shfl_sync(FULL, myc, li);      // jn = col4row[i]
            if (lane == li) SET4(si, c4r0, c4r1, c4r2, c4r3, j);
            j = jn;
            if (ii == cur) break;
        }
        __syncwarp();   // u_s/du_s visible before next phase
    }

    // ---- sum matched original entries, then cross-CTA completion ----
    float m = Cs[(base)     * NN + c4r0]
            + Cs[(base + 1) * NN + c4r1]
            + Cs[(base + 2) * NN + c4r2]
            + Cs[(base + 3) * NN + c4r3];
    #pragma unroll
    for (int off = 16; off > 0; off >>= 1)
        m += __shfl_down_sync(FULL, m, off);

    int last = 0;
    if (lane == 0) {
        g_partial[b] = m;
        __threadfence();
        last = (atomicAdd(&g_count, 1u) == BATCH - 1);
    }
    if (__shfl_sync(FULL, last, 0)) {
        __threadfence();
        volatile float* gp = g_partial;
        float s = gp[base] + gp[base + 1] + gp[base + 2] + gp[base + 3];
        #pragma unroll
        for (int off = 16; off > 0; off >>= 1)
            s += __shfl_down_sync(FULL, s, off);
        if (lane == 0) {
            out[0] = s * (1.0f / (float)(NN * BATCH));
            g_count = 0;                       // reset for next graph replay
        }
    }
}

extern "C" void kernel_launch(void* const* d_in, const int* in_sizes, int n_in,
                              void* d_out, int out_size) {
    (void)in_sizes; (void)n_in; (void)out_size;
    const float* D = (const float*)d_in[0];
    float* out = (float*)d_out;

    const int smem = NN * NN * (int)sizeof(float);   // 64KB dynamic
    cudaFuncSetAttribute(lsap_warp_kernel,
                         cudaFuncAttributeMaxDynamicSharedMemorySize, smem);

    lsap_warp_kernel<<<BATCH, 32, smem>>>(D, out);
}

// round 13
// speedup vs baseline: 1.1272x; 1.0891x over previous
#include <cuda_runtime.h>
#include <cuda_bf16.h>

// Batched LSAP -> mean of matched original entries, one warp per matrix.
// Normalization skipped (monotone affine => same optimal assignment).
//
// Lane L owns columns/rows {4L..4L+3}. Dijkstra argmin key packs BOTH the
// (truncated, order-preserved) sp value and row4col[col]+1 into 32 bits:
//   key = (fford(sp) & 0xFFFFFF00) | (row4col+1)
// row4col is injective over assigned columns and phase-constant, so the
// REDUX winner directly yields the next row r4 AND the popped value mv
// (reconstructed from the truncated bits) -- no post-REDUX shfl/LDS on the
// critical path. Sink steps (r4 field == 0) elect the column once per phase
// via ballot. Frozen columns hold key == FROZEN_KEY (fford(1e30)&~255) and
// their future reduced costs are EXACTLY 1e30 (fp absorption with w=-1e30),
// so rm_key >= FROZEN_KEY: no masking, and predecessors stay intact.

#define NN 128
#define BATCH 128
#define INF_F   1e30f
#define NEG_BIG -1e30f
#define DU_SENT -1e30f
#define FULL 0xffffffffu
#define VMASK 0xFFFFFF00u
#define FROZEN_KEY 0xF149F200u   /* fford(1e30f) & VMASK */

__device__ float g_partial[BATCH];
__device__ unsigned g_count = 0;

// order-preserving float <-> uint bijection
__device__ __forceinline__ unsigned fford(float f) {
    unsigned b = __float_as_uint(f);
    return b ^ (unsigned)(((int)b >> 31) | 0x80000000);
}
__device__ __forceinline__ float ffunord(unsigned u) {
    unsigned b = u ^ (unsigned)(((int)(~u) >> 31) | 0x80000000);
    return __uint_as_float(b);
}

#define SEL4(s, a0, a1, a2, a3) ((s) < 2 ? ((s) == 0 ? (a0) : (a1)) \
                                         : ((s) == 2 ? (a2) : (a3)))
#define SET4(s, a0, a1, a2, a3, val) do {            \
    if      ((s) == 0) a0 = (val);                   \
    else if ((s) == 1) a1 = (val);                   \
    else if ((s) == 2) a2 = (val);                   \
    else               a3 = (val); } while (0)

__global__ __launch_bounds__(32, 1)
void lsap_warp_kernel(const float* __restrict__ D, float* __restrict__ out) {
    extern __shared__ float Cs[];              // NN*NN floats (64KB)
    __shared__ float u_s[NN], du_s[NN], fz_s[NN];
    __shared__ int   claim_s[NN], c4r_s[NN];

    const int lane = threadIdx.x;
    const int b    = blockIdx.x;
    const int base = lane << 2;
    const unsigned jid0 = base, jid1 = base + 1, jid2 = base + 2, jid3 = base + 3;

    // ---- load cost matrix (coalesced float4) ----
    {
        const float4* src = reinterpret_cast<const float4*>(D + (size_t)b * NN * NN);
        float4* dst = reinterpret_cast<float4*>(Cs);
        #pragma unroll 8
        for (int k = lane; k < NN * NN / 4; k += 32) dst[k] = src[k];
    }
    *reinterpret_cast<float4*>(u_s + base) = make_float4(0.f, 0.f, 0.f, 0.f);
    *reinterpret_cast<int4*>(claim_s + base) =
        make_int4(0x7FFFFFFF, 0x7FFFFFFF, 0x7FFFFFFF, 0x7FFFFFFF);
    *reinterpret_cast<int4*>(c4r_s + base) = make_int4(-1, -1, -1, -1);
    __syncwarp();

    // ================= Phase A: column reduction =================
    float cm0 = INF_F, cm1 = INF_F, cm2 = INF_F, cm3 = INF_F;
    int   am0 = 0, am1 = 0, am2 = 0, am3 = 0;
    #pragma unroll 4
    for (int i = 0; i < NN; ++i) {
        const float4 cr = *reinterpret_cast<const float4*>(Cs + i * NN + base);
        if (cr.x < cm0) { cm0 = cr.x; am0 = i; }
        if (cr.y < cm1) { cm1 = cr.y; am1 = i; }
        if (cr.z < cm2) { cm2 = cr.z; am2 = i; }
        if (cr.w < cm3) { cm3 = cr.w; am3 = i; }
    }
    float v0 = cm0, v1 = cm1, v2 = cm2, v3 = cm3;

    atomicMin(&claim_s[am0], base);
    atomicMin(&claim_s[am1], base + 1);
    atomicMin(&claim_s[am2], base + 2);
    atomicMin(&claim_s[am3], base + 3);
    __syncwarp();
    int r4c0 = -1, r4c1 = -1, r4c2 = -1, r4c3 = -1;   // row4col (by column)
    if (claim_s[am0] == base)     { r4c0 = am0; c4r_s[am0] = base; }
    if (claim_s[am1] == base + 1) { r4c1 = am1; c4r_s[am1] = base + 1; }
    if (claim_s[am2] == base + 2) { r4c2 = am2; c4r_s[am2] = base + 2; }
    if (claim_s[am3] == base + 3) { r4c3 = am3; c4r_s[am3] = base + 3; }
    __syncwarp();
    const int4 ct = *reinterpret_cast<const int4*>(c4r_s + base);
    int c4r0 = ct.x, c4r1 = ct.y, c4r2 = ct.z, c4r3 = ct.w;  // col4row (by row)
    __syncwarp();

    // ================= Phase B: augmenting row reduction (2 sweeps) =========
    for (int pass = 0; pass < 2; ++pass) {
        for (int i = 0; i < NN; ++i) {
            const int mycI = SEL4(i & 3, c4r0, c4r1, c4r2, c4r3);
            if (__shfl_sync(FULL, mycI, i >> 2) >= 0) continue;

            const float4 cr = *reinterpret_cast<const float4*>(Cs + i * NN + base);
            const float t0 = cr.x - v0, t1 = cr.y - v1;
            const float t2 = cr.z - v2, t3 = cr.w - v3;
            unsigned k0 = (fford(t0) & 0xFFFFFF80u) | jid0;
            unsigned k1 = (fford(t1) & 0xFFFFFF80u) | jid1;
            unsigned k2 = (fford(t2) & 0xFFFFFF80u) | jid2;
            unsigned k3 = (fford(t3) & 0xFFFFFF80u) | jid3;
            unsigned key = min(min(k0, k1), min(k2, k3));
            key = __reduce_min_sync(FULL, key);
            const int j1 = (int)(key & 127u), s1 = j1 & 3, l1 = j1 >> 2;
            const float candt = SEL4(s1, t0, t1, t2, t3);
            const float min1  = __shfl_sync(FULL, candt, l1);   // exact

            float e0 = t0, e1 = t1, e2 = t2, e3 = t3;
            if (lane == l1) SET4(s1, e0, e1, e2, e3, INF_F);
            const float bv2  = fminf(fminf(e0, e1), fminf(e2, e3));
            const float min2 = ffunord(__reduce_min_sync(FULL, fford(bv2)));

            const int candr = SEL4(s1, r4c0, r4c1, r4c2, r4c3);
            const int kprev = __shfl_sync(FULL, candr, l1);
            if (lane == 0) u_s[i] = min2;
            if (lane == l1) {
                SET4(s1, r4c0, r4c1, r4c2, r4c3, i);
                if (min1 < min2) {
                    const float nv = SEL4(s1, v0, v1, v2, v3) - (min2 - min1);
                    SET4(s1, v0, v1, v2, v3, nv);
                }
            }
            if (lane == (i >> 2)) SET4(i & 3, c4r0, c4r1, c4r2, c4r3, j1);
            if (kprev >= 0 && lane == (kprev >> 2))
                SET4(kprev & 3, c4r0, c4r1, c4r2, c4r3, -1);
        }
    }
    __syncwarp();

    // ================= Phase C: shortest augmenting path ====================
    for (int cur = 0; cur < NN; ++cur) {
        const int mycC = SEL4(cur & 3, c4r0, c4r1, c4r2, c4r3);
        if (__shfl_sync(FULL, mycC, cur >> 2) >= 0) continue;

        // phase-constant packed row4col (+1, 8 bits); injective on assigned
        const unsigned q0 = (unsigned)(r4c0 + 1), q1 = (unsigned)(r4c1 + 1);
        const unsigned q2 = (unsigned)(r4c2 + 1), q3 = (unsigned)(r4c3 + 1);
        unsigned k0 = 0xFFFFFFFFu, k1 = 0xFFFFFFFFu,
                 k2 = 0xFFFFFFFFu, k3 = 0xFFFFFFFFu;   // sp keys
        int   p0 = 0, p1 = 0, p2 = 0, p3 = 0;           // predecessors
        float w0 = v0, w1 = v1, w2 = v2, w3 = v3;       // working duals
        *reinterpret_cast<float4*>(du_s + base) =
            make_float4(DU_SENT, DU_SENT, DU_SENT, DU_SENT);
        __syncwarp();
        if (lane == 0) du_s[cur] = 0.0f;

        float mv = 0.0f;
        int   i  = cur;
        int   sink;
        unsigned wb;                                     // winning key

        while (true) {
            const float c = mv - u_s[i];
            const float4 cr = *reinterpret_cast<const float4*>(Cs + i * NN + base);
            // frozen: w=-1e30 -> rm == exactly 1e30 -> key == FROZEN_KEY|q >= k
            const float rm0 = cr.x + (c - w0);
            const float rm1 = cr.y + (c - w1);
            const float rm2 = cr.z + (c - w2);
            const float rm3 = cr.w + (c - w3);
            const unsigned n0 = (fford(rm0) & VMASK) | q0;
            const unsigned n1 = (fford(rm1) & VMASK) | q1;
            const unsigned n2 = (fford(rm2) & VMASK) | q2;
            const unsigned n3 = (fford(rm3) & VMASK) | q3;
            if (n0 < k0) { k0 = n0; p0 = i; }
            if (n1 < k1) { k1 = n1; p1 = i; }
            if (n2 < k2) { k2 = n2; p2 = i; }
            if (n3 < k3) { k3 = n3; p3 = i; }

            wb = __reduce_min_sync(FULL, min(min(k0, k1), min(k2, k3)));
            mv = ffunord(wb & VMASK);                    // popped value (floor)
            const int r4f = (int)(wb & 0xFFu);           // row4col[j] + 1
            if (r4f == 0) break;                         // sink: elect j below
            // freeze winning column (unique key: r4 injective)
            if (wb == k0) { k0 = FROZEN_KEY; w0 = NEG_BIG; fz_s[jid0] = mv; }
            else if (wb == k1) { k1 = FROZEN_KEY; w1 = NEG_BIG; fz_s[jid1] = mv; }
            else if (wb == k2) { k2 = FROZEN_KEY; w2 = NEG_BIG; fz_s[jid2] = mv; }
            else if (wb == k3) { k3 = FROZEN_KEY; w3 = NEG_BIG; fz_s[jid3] = mv; }
            const int r4 = r4f - 1;
            if (lane == 0) du_s[r4] = mv;                // row r4 enters SR
            i = r4;
        }

        // elect sink column among (possibly tied) unassigned winners
        {
            int m = (k0 == wb) ? 1 : ((k1 == wb) ? 2 : ((k2 == wb) ? 3 : ((k3 == wb) ? 4 : 0)));
            const unsigned bal = __ballot_sync(FULL, m != 0);
            const int leader = __ffs((int)bal) - 1;
            const int jc = base + m - 1;
            sink = __shfl_sync(FULL, jc, leader);
        }

        __syncwarp();
        // dual updates (scipy _lsap closed form; sink's v-delta is exactly 0)
        const float mf = mv;
        {
            const float4 du = *reinterpret_cast<const float4*>(du_s + base);
            float4 uu = *reinterpret_cast<float4*>(u_s + base);
            if (du.x > -1e29f) uu.x += mf - du.x;
            if (du.y > -1e29f) uu.y += mf - du.y;
            if (du.z > -1e29f) uu.z += mf - du.z;
            if (du.w > -1e29f) uu.w += mf - du.w;
            *reinterpret_cast<float4*>(u_s + base) = uu;
        }
        {
            const float4 fz = *reinterpret_cast<const float4*>(fz_s + base);
            if (w0 == NEG_BIG) v0 -= mf - fz.x;
            if (w1 == NEG_BIG) v1 -= mf - fz.y;
            if (w2 == NEG_BIG) v2 -= mf - fz.z;
            if (w3 == NEG_BIG) v3 -= mf - fz.w;
        }

        // augment alternating path (cooperative shfl walk)
        int j = sink;
        while (true) {
            const int sj = j & 3, lj = j >> 2;
            const int myp = SEL4(sj, p0, p1, p2, p3);
            const int ii  = __shfl_sync(FULL, myp, lj);      // i = path[j]
            if (lane == lj) SET4(sj, r4c0, r4c1, r4c2, r4c3, ii);
            const int si = ii & 3, li = ii >> 2;
            const int myc = SEL4(si, c4r0, c4r1, c4r2, c4r3);
            const int jn  = __shfl_sync(FULL, myc, li);      // jn = col4row[i]
            if (lane == li) SET4(si, c4r0, c4r1, c4r2, c4r3, j);
            j = jn;
            if (ii == cur) break;
        }
        __syncwarp();
    }

    // ---- sum matched original entries, then cross-CTA completion ----
    float m = Cs[(base)     * NN + c4r0]
            + Cs[(base + 1) * NN + c4r1]
            + Cs[(base + 2) * NN + c4r2]
            + Cs[(base + 3) * NN + c4r3];
    #pragma unroll
    for (int off = 16; off > 0; off >>= 1)
        m += __shfl_down_sync(FULL, m, off);

    int last = 0;
    if (lane == 0) {
        g_partial[b] = m;
        __threadfence();
        last = (atomicAdd(&g_count, 1u) == BATCH - 1);
    }
    if (__shfl_sync(FULL, last, 0)) {
        __threadfence();
        volatile float* gp = g_partial;
        float s = gp[base] + gp[base + 1] + gp[base + 2] + gp[base + 3];
        #pragma unroll
        for (int off = 16; off > 0; off >>= 1)
            s += __shfl_down_sync(FULL, s, off);
        if (lane == 0) {
            out[0] = s * (1.0f / (float)(NN * BATCH));
            g_count = 0;                       // reset for next graph replay
        }
    }
}

extern "C" void kernel_launch(void* const* d_in, const int* in_sizes, int n_in,
                              void* d_out, int out_size) {
    (void)in_sizes; (void)n_in; (void)out_size;
    const float* D = (const float*)d_in[0];
    float* out = (float*)d_out;

    const int smem = NN * NN * (int)sizeof(float);   // 64KB dynamic
    cudaFuncSetAttribute(lsap_warp_kernel,
                         cudaFuncAttributeMaxDynamicSharedMemorySize, smem);

    lsap_warp_kernel<<<BATCH, 32, smem>>>(D, out);
}

// round 14
// speedup vs baseline: 1.2070x; 1.0708x over previous
#include <cuda_runtime.h>
#include <cuda_bf16.h>

// Batched LSAP -> mean of matched original entries, one warp per matrix.
// Normalization skipped (monotone affine => same optimal assignment).
//
// Lane L owns columns/rows {4L..4L+3}. Phase C (shortest augmenting path)
// carries the Dijkstra potential BIASED by +4.0 so every compared quantity is
// a positive float; for positive IEEE floats raw bit order == value order, so
// the argmin key is simply
//   key = (__float_as_uint(rm_biased) & 0xFFFFFF00) | (row4col[col]+1)
// (no order-preserving bijection in the hot loop). The REDUX winner yields the
// next row (low 8 bits) AND the popped biased potential (high bits) directly.
// The bias cancels exactly in all dual updates (differences of biased values).
// Frozen columns: w = -1e30 makes future rm == exactly 1e30 (fp absorption),
// key == FROZEN_KEY|q >= running key FROZEN_KEY, so frozen slots self-exclude
// and predecessors stay intact, with zero masking ops.

#define NN 128
#define BATCH 128
#define INF_F   1e30f
#define NEG_BIG -1e30f
#define DU_SENT -1e30f
#define BIAS    4.0f
#define FULL 0xffffffffu
#define VMASK 0xFFFFFF00u
#define FROZEN_KEY 0x7149F200u   /* __float_as_uint(1e30f) & VMASK */

__device__ float g_partial[BATCH];
__device__ unsigned g_count = 0;

#define SEL4(s, a0, a1, a2, a3) ((s) < 2 ? ((s) == 0 ? (a0) : (a1)) \
                                         : ((s) == 2 ? (a2) : (a3)))
#define SET4(s, a0, a1, a2, a3, val) do {            \
    if      ((s) == 0) a0 = (val);                   \
    else if ((s) == 1) a1 = (val);                   \
    else if ((s) == 2) a2 = (val);                   \
    else               a3 = (val); } while (0)

__global__ __launch_bounds__(32, 1)
void lsap_warp_kernel(const float* __restrict__ D, float* __restrict__ out) {
    extern __shared__ float Cs[];              // NN*NN floats (64KB)
    __shared__ float u_s[NN], du_s[NN], fz_s[NN];
    __shared__ int   claim_s[NN], c4r_s[NN];

    const int lane = threadIdx.x;
    const int b    = blockIdx.x;
    const int base = lane << 2;
    const unsigned jid0 = base, jid1 = base + 1, jid2 = base + 2, jid3 = base + 3;

    // ---- load cost matrix (coalesced float4) ----
    {
        const float4* src = reinterpret_cast<const float4*>(D + (size_t)b * NN * NN);
        float4* dst = reinterpret_cast<float4*>(Cs);
        #pragma unroll 8
        for (int k = lane; k < NN * NN / 4; k += 32) dst[k] = src[k];
    }
    *reinterpret_cast<float4*>(u_s + base) = make_float4(0.f, 0.f, 0.f, 0.f);
    *reinterpret_cast<int4*>(claim_s + base) =
        make_int4(0x7FFFFFFF, 0x7FFFFFFF, 0x7FFFFFFF, 0x7FFFFFFF);
    *reinterpret_cast<int4*>(c4r_s + base) = make_int4(-1, -1, -1, -1);
    __syncwarp();

    // ================= Phase A: column reduction =================
    float cm0 = INF_F, cm1 = INF_F, cm2 = INF_F, cm3 = INF_F;
    int   am0 = 0, am1 = 0, am2 = 0, am3 = 0;
    #pragma unroll 4
    for (int i = 0; i < NN; ++i) {
        const float4 cr = *reinterpret_cast<const float4*>(Cs + i * NN + base);
        if (cr.x < cm0) { cm0 = cr.x; am0 = i; }
        if (cr.y < cm1) { cm1 = cr.y; am1 = i; }
        if (cr.z < cm2) { cm2 = cr.z; am2 = i; }
        if (cr.w < cm3) { cm3 = cr.w; am3 = i; }
    }
    float v0 = cm0, v1 = cm1, v2 = cm2, v3 = cm3;

    atomicMin(&claim_s[am0], base);
    atomicMin(&claim_s[am1], base + 1);
    atomicMin(&claim_s[am2], base + 2);
    atomicMin(&claim_s[am3], base + 3);
    __syncwarp();
    int r4c0 = -1, r4c1 = -1, r4c2 = -1, r4c3 = -1;   // row4col (by column)
    if (claim_s[am0] == base)     { r4c0 = am0; c4r_s[am0] = base; }
    if (claim_s[am1] == base + 1) { r4c1 = am1; c4r_s[am1] = base + 1; }
    if (claim_s[am2] == base + 2) { r4c2 = am2; c4r_s[am2] = base + 2; }
    if (claim_s[am3] == base + 3) { r4c3 = am3; c4r_s[am3] = base + 3; }
    __syncwarp();
    const int4 ct = *reinterpret_cast<const int4*>(c4r_s + base);
    int c4r0 = ct.x, c4r1 = ct.y, c4r2 = ct.z, c4r3 = ct.w;  // col4row (by row)
    __syncwarp();

    // ================= Phase B: augmenting row reduction (2 sweeps) =========
    // t = C - v >= 0 exactly (v only decreases from column minima), so raw
    // float bits are order-correct keys; min2 reduction is full-precision.
    for (int pass = 0; pass < 2; ++pass) {
        for (int i = 0; i < NN; ++i) {
            const int mycI = SEL4(i & 3, c4r0, c4r1, c4r2, c4r3);
            if (__shfl_sync(FULL, mycI, i >> 2) >= 0) continue;

            const float4 cr = *reinterpret_cast<const float4*>(Cs + i * NN + base);
            const float t0 = cr.x - v0, t1 = cr.y - v1;
            const float t2 = cr.z - v2, t3 = cr.w - v3;
            unsigned k0 = (__float_as_uint(t0) & 0xFFFFFF80u) | jid0;
            unsigned k1 = (__float_as_uint(t1) & 0xFFFFFF80u) | jid1;
            unsigned k2 = (__float_as_uint(t2) & 0xFFFFFF80u) | jid2;
            unsigned k3 = (__float_as_uint(t3) & 0xFFFFFF80u) | jid3;
            unsigned key = min(min(k0, k1), min(k2, k3));
            key = __reduce_min_sync(FULL, key);
            const int j1 = (int)(key & 127u), s1 = j1 & 3, l1 = j1 >> 2;
            const float candt = SEL4(s1, t0, t1, t2, t3);
            const float min1  = __shfl_sync(FULL, candt, l1);   // exact

            float e0 = t0, e1 = t1, e2 = t2, e3 = t3;
            if (lane == l1) SET4(s1, e0, e1, e2, e3, INF_F);
            const float bv2  = fminf(fminf(e0, e1), fminf(e2, e3));
            const float min2 = __uint_as_float(
                __reduce_min_sync(FULL, __float_as_uint(bv2)));  // exact (t>=0)

            const int candr = SEL4(s1, r4c0, r4c1, r4c2, r4c3);
            const int kprev = __shfl_sync(FULL, candr, l1);
            if (lane == 0) u_s[i] = min2;
            if (lane == l1) {
                SET4(s1, r4c0, r4c1, r4c2, r4c3, i);
                if (min1 < min2) {
                    const float nv = SEL4(s1, v0, v1, v2, v3) - (min2 - min1);
                    SET4(s1, v0, v1, v2, v3, nv);
                }
            }
            if (lane == (i >> 2)) SET4(i & 3, c4r0, c4r1, c4r2, c4r3, j1);
            if (kprev >= 0 && lane == (kprev >> 2))
                SET4(kprev & 3, c4r0, c4r1, c4r2, c4r3, -1);
        }
    }
    __syncwarp();

    // ================= Phase C: shortest augmenting path ====================
    for (int cur = 0; cur < NN; ++cur) {
        const int mycC = SEL4(cur & 3, c4r0, c4r1, c4r2, c4r3);
        if (__shfl_sync(FULL, mycC, cur >> 2) >= 0) continue;

        // phase-constant packed row4col (+1, 8 bits); injective on assigned
        const unsigned q0 = (unsigned)(r4c0 + 1), q1 = (unsigned)(r4c1 + 1);
        const unsigned q2 = (unsigned)(r4c2 + 1), q3 = (unsigned)(r4c3 + 1);
        unsigned k0 = 0xFFFFFFFFu, k1 = 0xFFFFFFFFu,
                 k2 = 0xFFFFFFFFu, k3 = 0xFFFFFFFFu;   // biased sp keys
        int   p0 = 0, p1 = 0, p2 = 0, p3 = 0;           // predecessors
        float w0 = v0, w1 = v1, w2 = v2, w3 = v3;       // working duals
        *reinterpret_cast<float4*>(du_s + base) =
            make_float4(DU_SENT, DU_SENT, DU_SENT, DU_SENT);
        __syncwarp();
        if (lane == 0) du_s[cur] = BIAS;                 // biased zero

        float mb = BIAS;                                 // biased potential
        int   i  = cur;
        int   sink;
        unsigned wb;                                     // winning key

        while (true) {
            const float c = mb - u_s[i];
            const float4 cr = *reinterpret_cast<const float4*>(Cs + i * NN + base);
            // frozen: w=-1e30 -> rm == exactly 1e30 -> key == FROZEN_KEY|q >= k
            const float rm0 = cr.x + (c - w0);
            const float rm1 = cr.y + (c - w1);
            const float rm2 = cr.z + (c - w2);
            const float rm3 = cr.w + (c - w3);
            // rm biased positive => raw bits are order-correct
            const unsigned n0 = (__float_as_uint(rm0) & VMASK) | q0;
            const unsigned n1 = (__float_as_uint(rm1) & VMASK) | q1;
            const unsigned n2 = (__float_as_uint(rm2) & VMASK) | q2;
            const unsigned n3 = (__float_as_uint(rm3) & VMASK) | q3;
            if (n0 < k0) { k0 = n0; p0 = i; }
            if (n1 < k1) { k1 = n1; p1 = i; }
            if (n2 < k2) { k2 = n2; p2 = i; }
            if (n3 < k3) { k3 = n3; p3 = i; }

            wb = __reduce_min_sync(FULL, min(min(k0, k1), min(k2, k3)));
            mb = __uint_as_float(wb & VMASK);            // popped biased value
            const int r4f = (int)(wb & 0xFFu);           // row4col[j] + 1
            if (r4f == 0) break;                         // sink: elect j below
            // freeze winning column (unique key: r4 injective when r4f>0)
            if (wb == k0) { k0 = FROZEN_KEY; w0 = NEG_BIG; fz_s[jid0] = mb; }
            else if (wb == k1) { k1 = FROZEN_KEY; w1 = NEG_BIG; fz_s[jid1] = mb; }
            else if (wb == k2) { k2 = FROZEN_KEY; w2 = NEG_BIG; fz_s[jid2] = mb; }
            else if (wb == k3) { k3 = FROZEN_KEY; w3 = NEG_BIG; fz_s[jid3] = mb; }
            const int r4 = r4f - 1;
            if (lane == 0) du_s[r4] = mb;                // row r4 enters SR
            i = r4;
        }

        // elect sink column among (possibly tied) unassigned winners
        {
            int m = (k0 == wb) ? 1 : ((k1 == wb) ? 2 : ((k2 == wb) ? 3 : ((k3 == wb) ? 4 : 0)));
            const unsigned bal = __ballot_sync(FULL, m != 0);
            const int leader = __ffs((int)bal) - 1;
            const int jc = base + m - 1;
            sink = __shfl_sync(FULL, jc, leader);
        }

        __syncwarp();
        // dual updates: biases cancel exactly in (mbf - du) and (mbf - fz)
        const float mbf = mb;
        {
            const float4 du = *reinterpret_cast<const float4*>(du_s + base);
            float4 uu = *reinterpret_cast<float4*>(u_s + base);
            if (du.x > -1e29f) uu.x += mbf - du.x;
            if (du.y > -1e29f) uu.y += mbf - du.y;
            if (du.z > -1e29f) uu.z += mbf - du.z;
            if (du.w > -1e29f) uu.w += mbf - du.w;
            *reinterpret_cast<float4*>(u_s + base) = uu;
        }
        {
            const float4 fz = *reinterpret_cast<const float4*>(fz_s + base);
            if (w0 == NEG_BIG) v0 -= mbf - fz.x;
            if (w1 == NEG_BIG) v1 -= mbf - fz.y;
            if (w2 == NEG_BIG) v2 -= mbf - fz.z;
            if (w3 == NEG_BIG) v3 -= mbf - fz.w;
        }

        // augment alternating path (cooperative shfl walk)
        int j = sink;
        while (true) {
            const int sj = j & 3, lj = j >> 2;
            const int myp = SEL4(sj, p0, p1, p2, p3);
            const int ii  = __shfl_sync(FULL, myp, lj);      // i = path[j]
            if (lane == lj) SET4(sj, r4c0, r4c1, r4c2, r4c3, ii);
            const int si = ii & 3, li = ii >> 2;
            const int myc = SEL4(si, c4r0, c4r1, c4r2, c4r3);
            const int jn  = __shfl_sync(FULL, myc, li);      // jn = col4row[i]
            if (lane == li) SET4(si, c4r0, c4r1, c4r2, c4r3, j);
            j = jn;
            if (ii == cur) break;
        }
        __syncwarp();
    }

    // ---- sum matched original entries, then cross-CTA completion ----
    float m = Cs[(base)     * NN + c4r0]
            + Cs[(base + 1) * NN + c4r1]
            + Cs[(base + 2) * NN + c4r2]
            + Cs[(base + 3) * NN + c4r3];
    #pragma unroll
    for (int off = 16; off > 0; off >>= 1)
        m += __shfl_down_sync(FULL, m, off);

    int last = 0;
    if (lane == 0) {
        g_partial[b] = m;
        __threadfence();
        last = (atomicAdd(&g_count, 1u) == BATCH - 1);
    }
    if (__shfl_sync(FULL, last, 0)) {
        __threadfence();
        volatile float* gp = g_partial;
        float s = gp[base] + gp[base + 1] + gp[base + 2] + gp[base + 3];
        #pragma unroll
        for (int off = 16; off > 0; off >>= 1)
            s += __shfl_down_sync(FULL, s, off);
        if (lane == 0) {
            out[0] = s * (1.0f / (float)(NN * BATCH));
            g_count = 0;                       // reset for next graph replay
        }
    }
}

extern "C" void kernel_launch(void* const* d_in, const int* in_sizes, int n_in,
                              void* d_out, int out_size) {
    (void)in_sizes; (void)n_in; (void)out_size;
    const float* D = (const float*)d_in[0];
    float* out = (float*)d_out;

    const int smem = NN * NN * (int)sizeof(float);   // 64KB dynamic
    cudaFuncSetAttribute(lsap_warp_kernel,
                         cudaFuncAttributeMaxDynamicSharedMemorySize, smem);

    lsap_warp_kernel<<<BATCH, 32, smem>>>(D, out);
}

// round 15
// speedup vs baseline: 1.3992x; 1.1592x over previous
#include <cuda_runtime.h>
#include <cuda_bf16.h>

// Batched LSAP -> mean of matched original entries, one warp per matrix.
// Normalization skipped (monotone affine => same optimal assignment).
//
// Full Jonker-Volgenant pipeline per matrix (lane L owns cols/rows {4L..4L+3}):
//   A) column reduction (v[j]=min_i C[i,j], argmin rows claimed)
//   A') reduction transfer: for each assigned row i with match j1,
//       mu = min_{j!=j1}(C[i,j]-v[j]); u[i]=mu; v[j1]=C[i,j1]-mu.
//       v only decreases => C-v stays >= 0 (raw-bit REDUX remains exact).
//   B) 2x augmenting row reduction sweeps
//   C) shortest augmenting path with BIASED (+4) positive potentials:
//      raw float bits are order-correct, so the argmin key is
//        key = (bits(rm) & 0xFFFFFF00) | (row4col[col]+1)
//      and one __reduce_min_sync yields both next row and popped potential.
//      Frozen columns: w=-1e30 -> rm == exactly 1e30 -> self-excluding keys.
//      Frozen values fz and per-phase du seeds live in registers / vector init
//      (no per-step STS for fz, no per-phase extra syncwarp).

#define NN 128
#define BATCH 128
#define INF_F   1e30f
#define NEG_BIG -1e30f
#define DU_SENT -1e30f
#define BIAS    4.0f
#define FULL 0xffffffffu
#define VMASK 0xFFFFFF00u
#define FROZEN_KEY 0x7149F200u   /* __float_as_uint(1e30f) & VMASK */

__device__ float g_partial[BATCH];
__device__ unsigned g_count = 0;

#define SEL4(s, a0, a1, a2, a3) ((s) < 2 ? ((s) == 0 ? (a0) : (a1)) \
                                         : ((s) == 2 ? (a2) : (a3)))
#define SET4(s, a0, a1, a2, a3, val) do {            \
    if      ((s) == 0) a0 = (val);                   \
    else if ((s) == 1) a1 = (val);                   \
    else if ((s) == 2) a2 = (val);                   \
    else               a3 = (val); } while (0)

__global__ __launch_bounds__(32, 1)
void lsap_warp_kernel(const float* __restrict__ D, float* __restrict__ out) {
    extern __shared__ float Cs[];              // NN*NN floats (64KB)
    __shared__ float u_s[NN], du_s[NN];
    __shared__ int   claim_s[NN], c4r_s[NN];

    const int lane = threadIdx.x;
    const int b    = blockIdx.x;
    const int base = lane << 2;
    const unsigned jid0 = base, jid1 = base + 1, jid2 = base + 2, jid3 = base + 3;

    // ---- load cost matrix (coalesced float4) ----
    {
        const float4* src = reinterpret_cast<const float4*>(D + (size_t)b * NN * NN);
        float4* dst = reinterpret_cast<float4*>(Cs);
        #pragma unroll 8
        for (int k = lane; k < NN * NN / 4; k += 32) dst[k] = src[k];
    }
    *reinterpret_cast<float4*>(u_s + base) = make_float4(0.f, 0.f, 0.f, 0.f);
    *reinterpret_cast<int4*>(claim_s + base) =
        make_int4(0x7FFFFFFF, 0x7FFFFFFF, 0x7FFFFFFF, 0x7FFFFFFF);
    *reinterpret_cast<int4*>(c4r_s + base) = make_int4(-1, -1, -1, -1);
    __syncwarp();

    // ================= Phase A: column reduction =================
    float cm0 = INF_F, cm1 = INF_F, cm2 = INF_F, cm3 = INF_F;
    int   am0 = 0, am1 = 0, am2 = 0, am3 = 0;
    #pragma unroll 4
    for (int i = 0; i < NN; ++i) {
        const float4 cr = *reinterpret_cast<const float4*>(Cs + i * NN + base);
        if (cr.x < cm0) { cm0 = cr.x; am0 = i; }
        if (cr.y < cm1) { cm1 = cr.y; am1 = i; }
        if (cr.z < cm2) { cm2 = cr.z; am2 = i; }
        if (cr.w < cm3) { cm3 = cr.w; am3 = i; }
    }
    float v0 = cm0, v1 = cm1, v2 = cm2, v3 = cm3;

    atomicMin(&claim_s[am0], base);
    atomicMin(&claim_s[am1], base + 1);
    atomicMin(&claim_s[am2], base + 2);
    atomicMin(&claim_s[am3], base + 3);
    __syncwarp();
    int r4c0 = -1, r4c1 = -1, r4c2 = -1, r4c3 = -1;   // row4col (by column)
    if (claim_s[am0] == base)     { r4c0 = am0; c4r_s[am0] = base; }
    if (claim_s[am1] == base + 1) { r4c1 = am1; c4r_s[am1] = base + 1; }
    if (claim_s[am2] == base + 2) { r4c2 = am2; c4r_s[am2] = base + 2; }
    if (claim_s[am3] == base + 3) { r4c3 = am3; c4r_s[am3] = base + 3; }
    __syncwarp();
    const int4 ct = *reinterpret_cast<const int4*>(c4r_s + base);
    int c4r0 = ct.x, c4r1 = ct.y, c4r2 = ct.z, c4r3 = ct.w;  // col4row (by row)
    __syncwarp();

    // ============ Phase A': reduction transfer (assigned rows) =============
    for (int i = 0; i < NN; ++i) {
        const int mycI = SEL4(i & 3, c4r0, c4r1, c4r2, c4r3);
        const int j1 = __shfl_sync(FULL, mycI, i >> 2);
        if (j1 < 0) continue;                         // unassigned row

        const float4 cr = *reinterpret_cast<const float4*>(Cs + i * NN + base);
        float t0 = cr.x - v0, t1 = cr.y - v1;
        float t2 = cr.z - v2, t3 = cr.w - v3;
        const int l1 = j1 >> 2, s1 = j1 & 3;
        if (lane == l1) SET4(s1, t0, t1, t2, t3, INF_F);   // exclude j1
        const float bv = fminf(fminf(t0, t1), fminf(t2, t3));
        const float mu = __uint_as_float(
            __reduce_min_sync(FULL, __float_as_uint(bv)));  // exact (t>=0)
        if (lane == 0) u_s[i] = mu;
        if (lane == l1) {                              // v[j1] = C[i][j1] - mu
            const float cij = SEL4(s1, cr.x, cr.y, cr.z, cr.w);
            SET4(s1, v0, v1, v2, v3, cij - mu);
        }
    }
    __syncwarp();

    // ================= Phase B: augmenting row reduction (2 sweeps) =========
    for (int pass = 0; pass < 2; ++pass) {
        for (int i = 0; i < NN; ++i) {
            const int mycI = SEL4(i & 3, c4r0, c4r1, c4r2, c4r3);
            if (__shfl_sync(FULL, mycI, i >> 2) >= 0) continue;

            const float4 cr = *reinterpret_cast<const float4*>(Cs + i * NN + base);
            const float t0 = cr.x - v0, t1 = cr.y - v1;
            const float t2 = cr.z - v2, t3 = cr.w - v3;
            unsigned k0 = (__float_as_uint(t0) & 0xFFFFFF80u) | jid0;
            unsigned k1 = (__float_as_uint(t1) & 0xFFFFFF80u) | jid1;
            unsigned k2 = (__float_as_uint(t2) & 0xFFFFFF80u) | jid2;
            unsigned k3 = (__float_as_uint(t3) & 0xFFFFFF80u) | jid3;
            unsigned key = min(min(k0, k1), min(k2, k3));
            key = __reduce_min_sync(FULL, key);
            const int j1 = (int)(key & 127u), s1 = j1 & 3, l1 = j1 >> 2;
            const float candt = SEL4(s1, t0, t1, t2, t3);
            const float min1  = __shfl_sync(FULL, candt, l1);   // exact

            float e0 = t0, e1 = t1, e2 = t2, e3 = t3;
            if (lane == l1) SET4(s1, e0, e1, e2, e3, INF_F);
            const float bv2  = fminf(fminf(e0, e1), fminf(e2, e3));
            const float min2 = __uint_as_float(
                __reduce_min_sync(FULL, __float_as_uint(bv2)));  // exact (t>=0)

            const int candr = SEL4(s1, r4c0, r4c1, r4c2, r4c3);
            const int kprev = __shfl_sync(FULL, candr, l1);
            if (lane == 0) u_s[i] = min2;
            if (lane == l1) {
                SET4(s1, r4c0, r4c1, r4c2, r4c3, i);
                if (min1 < min2) {
                    const float nv = SEL4(s1, v0, v1, v2, v3) - (min2 - min1);
                    SET4(s1, v0, v1, v2, v3, nv);
                }
            }
            if (lane == (i >> 2)) SET4(i & 3, c4r0, c4r1, c4r2, c4r3, j1);
            if (kprev >= 0 && lane == (kprev >> 2))
                SET4(kprev & 3, c4r0, c4r1, c4r2, c4r3, -1);
        }
    }
    __syncwarp();

    // ================= Phase C: shortest augmenting path ====================
    for (int cur = 0; cur < NN; ++cur) {
        const int mycC = SEL4(cur & 3, c4r0, c4r1, c4r2, c4r3);
        if (__shfl_sync(FULL, mycC, cur >> 2) >= 0) continue;

        // phase-constant packed row4col (+1, 8 bits); injective on assigned
        const unsigned q0 = (unsigned)(r4c0 + 1), q1 = (unsigned)(r4c1 + 1);
        const unsigned q2 = (unsigned)(r4c2 + 1), q3 = (unsigned)(r4c3 + 1);
        unsigned k0 = 0xFFFFFFFFu, k1 = 0xFFFFFFFFu,
                 k2 = 0xFFFFFFFFu, k3 = 0xFFFFFFFFu;   // biased sp keys
        int   p0 = 0, p1 = 0, p2 = 0, p3 = 0;           // predecessors
        float w0 = v0, w1 = v1, w2 = v2, w3 = v3;       // working duals
        float fz0 = 0, fz1 = 0, fz2 = 0, fz3 = 0;       // frozen values (regs)
        {   // du init with BIAS seeded at cur's owner slot (no extra STS/sync)
            float4 di = make_float4(DU_SENT, DU_SENT, DU_SENT, DU_SENT);
            if (lane == (cur >> 2)) {
                if      ((cur & 3) == 0) di.x = BIAS;
                else if ((cur & 3) == 1) di.y = BIAS;
                else if ((cur & 3) == 2) di.z = BIAS;
                else                     di.w = BIAS;
            }
            *reinterpret_cast<float4*>(du_s + base) = di;
        }

        float mb = BIAS;                                 // biased potential
        int   i  = cur;
        int   sink;
        unsigned wb;                                     // winning key

        while (true) {
            const float c = mb - u_s[i];
            const float4 cr = *reinterpret_cast<const float4*>(Cs + i * NN + base);
            // frozen: w=-1e30 -> rm == exactly 1e30 -> key == FROZEN_KEY|q >= k
            const float rm0 = cr.x + (c - w0);
            const float rm1 = cr.y + (c - w1);
            const float rm2 = cr.z + (c - w2);
            const float rm3 = cr.w + (c - w3);
            // rm biased positive => raw bits are order-correct
            const unsigned n0 = (__float_as_uint(rm0) & VMASK) | q0;
            const unsigned n1 = (__float_as_uint(rm1) & VMASK) | q1;
            const unsigned n2 = (__float_as_uint(rm2) & VMASK) | q2;
            const unsigned n3 = (__float_as_uint(rm3) & VMASK) | q3;
            if (n0 < k0) { k0 = n0; p0 = i; }
            if (n1 < k1) { k1 = n1; p1 = i; }
            if (n2 < k2) { k2 = n2; p2 = i; }
            if (n3 < k3) { k3 = n3; p3 = i; }

            wb = __reduce_min_sync(FULL, min(min(k0, k1), min(k2, k3)));
            mb = __uint_as_float(wb & VMASK);            // popped biased value
            const int r4f = (int)(wb & 0xFFu);           // row4col[j] + 1
            if (r4f == 0) break;                         // sink: elect j below
            // freeze winning column (unique key: r4 injective when r4f>0)
            if (wb == k0) { k0 = FROZEN_KEY; w0 = NEG_BIG; fz0 = mb; }
            else if (wb == k1) { k1 = FROZEN_KEY; w1 = NEG_BIG; fz1 = mb; }
            else if (wb == k2) { k2 = FROZEN_KEY; w2 = NEG_BIG; fz2 = mb; }
            else if (wb == k3) { k3 = FROZEN_KEY; w3 = NEG_BIG; fz3 = mb; }
            const int r4 = r4f - 1;
            if (lane == 0) du_s[r4] = mb;                // row r4 enters SR
            i = r4;
        }

        // elect sink column among (possibly tied) unassigned winners
        {
            int m = (k0 == wb) ? 1 : ((k1 == wb) ? 2 : ((k2 == wb) ? 3 : ((k3 == wb) ? 4 : 0)));
            const unsigned bal = __ballot_sync(FULL, m != 0);
            const int leader = __ffs((int)bal) - 1;
            const int jc = base + m - 1;
            sink = __shfl_sync(FULL, jc, leader);
        }

        __syncwarp();     // lane0's du_s stores -> owner-lane reads
        // dual updates: biases cancel exactly in (mbf - du) and (mbf - fz)
        const float mbf = mb;
        {
            const float4 du = *reinterpret_cast<const float4*>(du_s + base);
            float4 uu = *reinterpret_cast<float4*>(u_s + base);
            if (du.x > -1e29f) uu.x += mbf - du.x;
            if (du.y > -1e29f) uu.y += mbf - du.y;
            if (du.z > -1e29f) uu.z += mbf - du.z;
            if (du.w > -1e29f) uu.w += mbf - du.w;
            *reinterpret_cast<float4*>(u_s + base) = uu;
        }
        if (w0 == NEG_BIG) v0 -= mbf - fz0;
        if (w1 == NEG_BIG) v1 -= mbf - fz1;
        if (w2 == NEG_BIG) v2 -= mbf - fz2;
        if (w3 == NEG_BIG) v3 -= mbf - fz3;

        // augment alternating path (cooperative shfl walk)
        int j = sink;
        while (true) {
            const int sj = j & 3, lj = j >> 2;
            const int myp = SEL4(sj, p0, p1, p2, p3);
            const int ii  = __shfl_sync(FULL, myp, lj);      // i = path[j]
            if (lane == lj) SET4(sj, r4c0, r4c1, r4c2, r4c3, ii);
            const int si = ii & 3, li = ii >> 2;
            const int myc = SEL4(si, c4r0, c4r1, c4r2, c4r3);
            const int jn  = __shfl_sync(FULL, myc, li);      // jn = col4row[i]
            if (lane == li) SET4(si, c4r0, c4r1, c4r2, c4r3, j);
            j = jn;
            if (ii == cur) break;
        }
        __syncwarp();     // u_s updates visible before next phase reads
    }

    // ---- sum matched original entries, then cross-CTA completion ----
    float m = Cs[(base)     * NN + c4r0]
            + Cs[(base + 1) * NN + c4r1]
            + Cs[(base + 2) * NN + c4r2]
            + Cs[(base + 3) * NN + c4r3];
    #pragma unroll
    for (int off = 16; off > 0; off >>= 1)
        m += __shfl_down_sync(FULL, m, off);

    int last = 0;
    if (lane == 0) {
        g_partial[b] = m;
        __threadfence();
        last = (atomicAdd(&g_count, 1u) == BATCH - 1);
    }
    if (__shfl_sync(FULL, last, 0)) {
        __threadfence();
        volatile float* gp = g_partial;
        float s = gp[base] + gp[base + 1] + gp[base + 2] + gp[base + 3];
        #pragma unroll
        for (int off = 16; off > 0; off >>= 1)
            s += __shfl_down_sync(FULL, s, off);
        if (lane == 0) {
            out[0] = s * (1.0f / (float)(NN * BATCH));
            g_count = 0;                       // reset for next graph replay
        }
    }
}

extern "C" void kernel_launch(void* const* d_in, const int* in_sizes, int n_in,
                              void* d_out, int out_size) {
    (void)in_sizes; (void)n_in; (void)out_size;
    const float* D = (const float*)d_in[0];
    float* out = (float*)d_out;

    const int smem = NN * NN * (int)sizeof(float);   // 64KB dynamic
    cudaFuncSetAttribute(lsap_warp_kernel,
                         cudaFuncAttributeMaxDynamicSharedMemorySize, smem);

    lsap_warp_kernel<<<BATCH, 32, smem>>>(D, out);
}